// round 10
// baseline (speedup 1.0000x reference)
#include <cuda_runtime.h>

// Problem constants
#define NB   4096
#define DIN  1856
#define HH   128
#define WB   191       // band half-width: tail < 7e-8 absolute, negligible vs 1e-3
#define BWID 383
#define GRID 128       // persistent blocks, all co-resident
#define RPB  32        // rows per block
#define NJ   416       // padded window length: j in [r0-191, r0+224)
#define SA   36        // transposed-activation stride (mult of 4 -> 16B aligned)

typedef unsigned long long ull;

// Persistent device scratch (zero-initialized at module load)
__device__ float g_bandT[GRID * NJ * RPB];   // [blk][jj][r], 6.8 MB
__device__ float g_h[NB * HH];
__device__ float g_ybuf[2][NB * HH];
__device__ int g_bar_count = 0;
__device__ unsigned g_bar_gen = 0;

// ---------------------------------------------------------------------------
// f32x2 packed-math helpers
// ---------------------------------------------------------------------------
__device__ __forceinline__ ull dup2(float x) {
    ull r; asm("mov.b64 %0, {%1, %1};" : "=l"(r) : "f"(x)); return r;
}
__device__ __forceinline__ void ffma2(ull& d, ull a, ull b) {
    asm("fma.rn.f32x2 %0, %1, %2, %0;" : "+l"(d) : "l"(a), "l"(b));
}
__device__ __forceinline__ float2 unpk(ull v) {
    float2 f; asm("mov.b64 {%0, %1}, %2;" : "=f"(f.x), "=f"(f.y) : "l"(v));
    return f;
}

// 8 rows x 2 cols microtile step, both operands via pointer (smem).
__device__ __forceinline__ void step8(ull acc[4][2],
                                      const float* __restrict__ aBase,
                                      const float* __restrict__ bBase)
{
    ulonglong2 a1 = *(const ulonglong2*)(aBase);       // rows (0,1),(2,3)
    ulonglong2 a2 = *(const ulonglong2*)(aBase + 4);   // rows (4,5),(6,7)
    float2 wv = *(const float2*)(bBase);
    ull w0 = dup2(wv.x), w1 = dup2(wv.y);
    ffma2(acc[0][0], a1.x, w0); ffma2(acc[0][1], a1.x, w1);
    ffma2(acc[1][0], a1.y, w0); ffma2(acc[1][1], a1.y, w1);
    ffma2(acc[2][0], a2.x, w0); ffma2(acc[2][1], a2.x, w1);
    ffma2(acc[3][0], a2.y, w0); ffma2(acc[3][1], a2.y, w1);
}

// Same, with the 2-col operand passed by value (already loaded from global).
__device__ __forceinline__ void step8v(ull acc[4][2],
                                       const float* __restrict__ aBase,
                                       float2 wv)
{
    ulonglong2 a1 = *(const ulonglong2*)(aBase);
    ulonglong2 a2 = *(const ulonglong2*)(aBase + 4);
    ull w0 = dup2(wv.x), w1 = dup2(wv.y);
    ffma2(acc[0][0], a1.x, w0); ffma2(acc[0][1], a1.x, w1);
    ffma2(acc[1][0], a1.y, w0); ffma2(acc[1][1], a1.y, w1);
    ffma2(acc[2][0], a2.x, w0); ffma2(acc[2][1], a2.x, w1);
    ffma2(acc[3][0], a2.y, w0); ffma2(acc[3][1], a2.y, w1);
}

// ---------------------------------------------------------------------------
// Grid-wide barrier (all GRID blocks resident by construction).
// ---------------------------------------------------------------------------
__device__ __forceinline__ void grid_sync_dev()
{
    __syncthreads();
    if (threadIdx.x == 0) {
        __threadfence();
        unsigned gen = *((volatile unsigned*)&g_bar_gen);
        if (atomicAdd(&g_bar_count, 1) == (int)gridDim.x - 1) {
            g_bar_count = 0;
            __threadfence();
            *((volatile unsigned*)&g_bar_gen) = gen + 1;
        } else {
            while (*((volatile unsigned*)&g_bar_gen) == gen) { }
        }
        __threadfence();
    }
    __syncthreads();
}

// ---------------------------------------------------------------------------
// Kernel 1: build normalized band adjacency, written TRANSPOSED per ode block:
// g_bandT[blk][jj][r] with blk = i/32, r = i%32, jj = d+191 + r.
// Cells never written stay 0 (zero-init .bss; values are launch-invariant).
// ---------------------------------------------------------------------------
__global__ void __launch_bounds__(384) build_band_kernel(
    const int* __restrict__ spk, const float* __restrict__ mmask)
{
    int i = blockIdx.x;
    int t = threadIdx.x;            // 0..383 -> d = t - 191
    int d = t - WB;
    int j = i + d;

    float val = 0.0f;
    bool valid = (t < BWID && j >= 0 && j < NB);
    if (valid) {
        if (d == 0) {
            val = 1.0f;
        } else {
            float temporal = expf(-0.1f * fabsf((float)d));
            if (spk[i] == spk[j]) {
                val = 0.8f * temporal;
            } else {
                float md = fabsf(mmask[i*3+0] - mmask[j*3+0])
                         + fabsf(mmask[i*3+1] - mmask[j*3+1])
                         + fabsf(mmask[i*3+2] - mmask[j*3+2]);
                float mod_sim = 1.0f - md * (1.0f/3.0f);
                val = 0.5f * temporal * mod_sim;
            }
        }
    }

    __shared__ float sd[384];
    sd[t] = val;
    __syncthreads();
    // 384 = 256 + 128: fold the tail first, then power-of-2 reduction.
    if (t < 128) sd[t] += sd[t + 256];
    __syncthreads();
    for (int s = 128; s > 0; s >>= 1) {
        if (t < s) sd[t] += sd[t + s];
        __syncthreads();
    }
    float inv = 1.0f / (sd[0] + 1e-8f);

    if (valid) {
        int blk = i >> 5, r = i & 31;
        int jj = t + r;                       // dd = t, jj = dd + r in [0, 414)
        g_bandT[(blk * NJ + jj) * RPB + r] = val * inv;
    }
}

// ---------------------------------------------------------------------------
// Kernel 2: projection h0 = X @ Wp + bp.  f32x2, 8x2 microtile, 256 threads.
// ---------------------------------------------------------------------------
__global__ void __launch_bounds__(256) proj_kernel(
    const float* __restrict__ X, const float* __restrict__ Wp,
    const float* __restrict__ bp)
{
    __shared__ __align__(16) float As[32 * SA];
    __shared__ __align__(16) float Bs[32 * 128];
    const int m0  = blockIdx.x * RPB;
    const int tid = threadIdx.x;
    const int rg  = tid >> 6;        // 0..3 -> rows 8rg..8rg+7 (warp-uniform)
    const int cg  = tid & 63;        // cols 2cg, 2cg+1

    ull acc[4][2];
#pragma unroll
    for (int a = 0; a < 4; a++) { acc[a][0] = 0ull; acc[a][1] = 0ull; }

    const int ar  = tid >> 3;
    const int ak4 = (tid & 7) * 4;

    for (int k0 = 0; k0 < DIN; k0 += 32) {
        {
            float4 v = *(const float4*)&X[(m0 + ar) * DIN + k0 + ak4];
            As[(ak4+0)*SA + ar] = v.x; As[(ak4+1)*SA + ar] = v.y;
            As[(ak4+2)*SA + ar] = v.z; As[(ak4+3)*SA + ar] = v.w;
        }
#pragma unroll
        for (int i = tid; i < 1024; i += 256) {
            int k = i >> 5, c4 = (i & 31) * 4;
            *(float4*)&Bs[k*128 + c4] = *(const float4*)&Wp[(k0 + k) * HH + c4];
        }
        __syncthreads();
#pragma unroll 8
        for (int k = 0; k < 32; k++)
            step8(acc, &As[k*SA + 8*rg], &Bs[k*128 + 2*cg]);
        __syncthreads();
    }

    float2 bb = *(const float2*)&bp[2*cg];
#pragma unroll
    for (int q = 0; q < 4; q++) {
        float2 f0 = unpk(acc[q][0]);
        float2 f1 = unpk(acc[q][1]);
        int r_even = m0 + 8*rg + 2*q;
        float2 o0 = make_float2(f0.x + bb.x, f1.x + bb.y);
        float2 o1 = make_float2(f0.y + bb.x, f1.y + bb.y);
        *(float2*)&g_h[r_even * HH + 2*cg]           = o0;
        *(float2*)&g_ybuf[0][r_even * HH + 2*cg]     = o0;
        *(float2*)&g_h[(r_even+1) * HH + 2*cg]       = o1;
        *(float2*)&g_ybuf[0][(r_even+1) * HH + 2*cg] = o1;
    }
}

// ---------------------------------------------------------------------------
// Kernel 3: persistent ODE kernel.
// smem: bandT (53KB, loaded once) + W1 (131KB, once) + y^T + hn/z^T.
// Per stage: sync-free LDG matvec -> mlp1 -> tanh -> mlp2(W2 via LDG) ->
// RK4 epilogue -> grid sync.  3 syncthreads/stage.
// ---------------------------------------------------------------------------
#define SBT_FLOATS (NJ * RPB)        // 13312
#define SW1_FLOATS (256 * 128)       // 32768
#define SYT_FLOATS (128 * SA)        // 4608
#define SAT_FLOATS (128 * SA)        // 4608
#define SMEM_FLOATS (SBT_FLOATS + SW1_FLOATS + SYT_FLOATS + SAT_FLOATS)
#define SMEM_BYTES  (SMEM_FLOATS * 4)   // 221184 B

__global__ void __launch_bounds__(256, 1) ode_kernel(
    const float* __restrict__ W1, const float* __restrict__ b1,
    const float* __restrict__ W2, const float* __restrict__ b2,
    float* __restrict__ outp)
{
    extern __shared__ __align__(16) float smem[];
    float* sBT = smem;                        // [NJ][32]
    float* sW1 = sBT + SBT_FLOATS;            // [256][128]
    float* sYT = sW1 + SW1_FLOATS;            // [128][SA]  y^T (own rows)
    float* sAt = sYT + SYT_FLOATS;            // [128][SA]  hn^T, then z^T

    const int tid = threadIdx.x;
    const int rg  = tid >> 6;                 // warp-uniform row group
    const int cg  = tid & 63;                 // cols 2cg, 2cg+1
    const int r0  = blockIdx.x * RPB;

    // one-time staging: bandT (coalesced), W1, y0^T
    {
        const float4* src = (const float4*)(g_bandT + blockIdx.x * SBT_FLOATS);
#pragma unroll
        for (int i = tid; i < SBT_FLOATS/4; i += 256)
            *(float4*)&sBT[i*4] = src[i];
    }
#pragma unroll
    for (int i = tid; i < SW1_FLOATS/4; i += 256)
        *(float4*)&sW1[i*4] = *(const float4*)&W1[i*4];
#pragma unroll
    for (int i = tid; i < 4096; i += 256) {
        int r = i >> 7, c = i & 127;
        sYT[c*SA + r] = g_ybuf[0][(r0 + r) * HH + c];
    }

    // persistent register state: rows 8rg..8rg+7, cols 2cg, 2cg+1
    float hreg[8][2], rk[8][2];
#pragma unroll
    for (int i = 0; i < 8; i++) {
        float2 v = *(const float2*)&g_h[(r0 + 8*rg + i) * HH + 2*cg];
        hreg[i][0] = v.x; hreg[i][1] = v.y;
    }
    float2 b1v = *(const float2*)&b1[2*cg];
    float2 b2v = *(const float2*)&b2[2*cg];
    const float dt = 0.25f;
    __syncthreads();

#pragma unroll 1
    for (int st = 0; st < 16; st++) {
        const int s = st & 3;
        const float* __restrict__ yin  = g_ybuf[st & 1];
        float* __restrict__       yout = g_ybuf[(st + 1) & 1];

        // ---- banded matvec, sync-free: y direct from L2, band from smem ----
        ull macc[4][2];
#pragma unroll
        for (int a = 0; a < 4; a++) { macc[a][0] = 0ull; macc[a][1] = 0ull; }
        {
            const int jbase = r0 - WB;
#pragma unroll 8
            for (int jj = 0; jj < NJ; jj++) {
                int j  = jbase + jj;
                int jc = min(max(j, 0), NB - 1);       // band=0 covers OOB
                float2 yv = *(const float2*)&yin[jc * HH + 2*cg];
                step8v(macc, &sBT[jj * RPB + 8*rg], yv);
            }
        }

        // ---- stage hn^T into sAt ----
#pragma unroll
        for (int q = 0; q < 4; q++)
#pragma unroll
            for (int c = 0; c < 2; c++) {
                float2 f = unpk(macc[q][c]);
                int col = 2*cg + c;
                sAt[col*SA + 8*rg + 2*q]     = f.x;
                sAt[col*SA + 8*rg + 2*q + 1] = f.y;
            }
        __syncthreads();

        // ---- mlp1: [y | hn] @ W1 ----
        ull acc1[4][2];
#pragma unroll
        for (int a = 0; a < 4; a++) { acc1[a][0] = 0ull; acc1[a][1] = 0ull; }
#pragma unroll 8
        for (int k = 0; k < 128; k++)
            step8(acc1, &sYT[k*SA + 8*rg], &sW1[k*128 + 2*cg]);
#pragma unroll 8
        for (int k = 0; k < 128; k++)
            step8(acc1, &sAt[k*SA + 8*rg], &sW1[(128 + k)*128 + 2*cg]);
        __syncthreads();                      // all hn^T reads done

        // ---- z = tanh(acc1 + b1) -> z^T into sAt ----
#pragma unroll
        for (int q = 0; q < 4; q++)
#pragma unroll
            for (int c = 0; c < 2; c++) {
                float2 f = unpk(acc1[q][c]);
                float bb = c ? b1v.y : b1v.x;
                int col = 2*cg + c;
                sAt[col*SA + 8*rg + 2*q]     = tanhf(f.x + bb);
                sAt[col*SA + 8*rg + 2*q + 1] = tanhf(f.y + bb);
            }
        __syncthreads();

        // ---- mlp2: k = z @ W2 + b2  (W2 streamed from L2) ----
        ull acc2[4][2];
#pragma unroll
        for (int a = 0; a < 4; a++) { acc2[a][0] = 0ull; acc2[a][1] = 0ull; }
#pragma unroll 8
        for (int k = 0; k < 128; k++) {
            float2 wv = *(const float2*)&W2[k*128 + 2*cg];
            step8v(acc2, &sAt[k*SA + 8*rg], wv);
        }

        // ---- RK4 epilogue ----
        {
            const float wq = (s == 0 || s == 3) ? dt * (1.0f/6.0f) : dt * (1.0f/3.0f);
            const float cq = (s == 2) ? dt : 0.5f * dt;
            float kvals[8][2];
#pragma unroll
            for (int q = 0; q < 4; q++)
#pragma unroll
                for (int c = 0; c < 2; c++) {
                    float2 f = unpk(acc2[q][c]);
                    float bb = c ? b2v.y : b2v.x;
                    kvals[2*q][c]   = f.x + bb;
                    kvals[2*q+1][c] = f.y + bb;
                }
            float yn[8][2];
#pragma unroll
            for (int i = 0; i < 8; i++)
#pragma unroll
                for (int c = 0; c < 2; c++) {
                    float kv = kvals[i][c];
                    if (s == 0) rk[i][c] = hreg[i][c] + wq * kv;
                    else        rk[i][c] += wq * kv;
                    if (s == 3) { hreg[i][c] = rk[i][c]; yn[i][c] = rk[i][c]; }
                    else        yn[i][c] = hreg[i][c] + cq * kv;
                }
            // write y to global (for neighbors) and y^T to smem (own mlp1)
#pragma unroll
            for (int i = 0; i < 8; i++) {
                int row = 8*rg + i;
                int idx = (r0 + row) * HH + 2*cg;
                float2 o = make_float2(yn[i][0], yn[i][1]);
                *(float2*)&yout[idx] = o;
                sYT[(2*cg+0)*SA + row] = yn[i][0];
                sYT[(2*cg+1)*SA + row] = yn[i][1];
                if (st == 15) *(float2*)&outp[idx] = o;
            }
        }

        grid_sync_dev();
    }
}

// ---------------------------------------------------------------------------
extern "C" void kernel_launch(void* const* d_in, const int* in_sizes, int n_in,
                              void* d_out, int out_size)
{
    (void)in_sizes; (void)n_in; (void)out_size;
    const float* features = (const float*)d_in[0];
    const int*   spk      = (const int*)  d_in[1];
    const float* mmask    = (const float*)d_in[2];
    const float* Wp       = (const float*)d_in[3];
    const float* bp       = (const float*)d_in[4];
    const float* W1       = (const float*)d_in[5];
    const float* b1       = (const float*)d_in[6];
    const float* W2       = (const float*)d_in[7];
    const float* b2       = (const float*)d_in[8];
    float* out = (float*)d_out;

    static int attr_done = 0;
    if (!attr_done) {
        cudaFuncSetAttribute(ode_kernel,
                             cudaFuncAttributeMaxDynamicSharedMemorySize,
                             SMEM_BYTES);
        attr_done = 1;
    }

    build_band_kernel<<<NB, 384>>>(spk, mmask);
    proj_kernel<<<GRID, 256>>>(features, Wp, bp);
    ode_kernel<<<GRID, 256, SMEM_BYTES>>>(W1, b1, W2, b2, out);
}

// round 11
// speedup vs baseline: 1.5664x; 1.5664x over previous
#include <cuda_runtime.h>

// Problem constants
#define NB   4096
#define DIN  1856
#define HH   128
#define WB2  140       // truncated half-width: tail ~1.3e-5 rel, safe vs 1e-3
#define BSTR 384       // band row stride (t = d+191, t in [0,383); t=383 stays 0)
#define GRID 128       // persistent blocks, all co-resident
#define RPB  32        // rows per block
#define CH   48        // matvec chunk rows
#define NCH  7         // 7*48 = 336 >= 2*140+32
#define SA   36        // transposed-activation stride
#define NT   512       // threads per block

typedef unsigned long long ull;

// Persistent device scratch (zero-initialized at module load)
__device__ float g_band[NB * BSTR];
__device__ float g_h[NB * HH];
__device__ float g_ybuf[2][NB * HH];
__device__ int g_bar_count = 0;
__device__ unsigned g_bar_gen = 0;

// ---------------------------------------------------------------------------
// f32x2 packed-math helpers
// ---------------------------------------------------------------------------
__device__ __forceinline__ ull dup2(float x) {
    ull r; asm("mov.b64 %0, {%1, %1};" : "=l"(r) : "f"(x)); return r;
}
__device__ __forceinline__ void ffma2(ull& d, ull a, ull b) {
    asm("fma.rn.f32x2 %0, %1, %2, %0;" : "+l"(d) : "l"(a), "l"(b));
}
__device__ __forceinline__ float2 unpk(ull v) {
    float2 f; asm("mov.b64 {%0, %1}, %2;" : "=f"(f.x), "=f"(f.y) : "l"(v));
    return f;
}

// 4 rows x 2 cols microtile: 1 LDS.128 (rows, f32x2 pairs) + 1 LDS.64 (cols).
__device__ __forceinline__ void step4(ull acc[2][2],
                                      const float* __restrict__ aBase,
                                      const float* __restrict__ bBase)
{
    ulonglong2 a = *(const ulonglong2*)(aBase);        // rows (0,1),(2,3)
    float2 wv = *(const float2*)(bBase);
    ull w0 = dup2(wv.x), w1 = dup2(wv.y);
    ffma2(acc[0][0], a.x, w0); ffma2(acc[0][1], a.x, w1);
    ffma2(acc[1][0], a.y, w0); ffma2(acc[1][1], a.y, w1);
}
__device__ __forceinline__ void step4v(ull acc[2][2],
                                       const float* __restrict__ aBase,
                                       float2 wv)
{
    ulonglong2 a = *(const ulonglong2*)(aBase);
    ull w0 = dup2(wv.x), w1 = dup2(wv.y);
    ffma2(acc[0][0], a.x, w0); ffma2(acc[0][1], a.x, w1);
    ffma2(acc[1][0], a.y, w0); ffma2(acc[1][1], a.y, w1);
}

// ---------------------------------------------------------------------------
// Grid-wide barrier (all GRID blocks resident by construction).
// ---------------------------------------------------------------------------
__device__ __forceinline__ void grid_sync_dev()
{
    __syncthreads();
    if (threadIdx.x == 0) {
        __threadfence();
        unsigned gen = *((volatile unsigned*)&g_bar_gen);
        if (atomicAdd(&g_bar_count, 1) == (int)gridDim.x - 1) {
            g_bar_count = 0;
            __threadfence();
            *((volatile unsigned*)&g_bar_gen) = gen + 1;
        } else {
            while (*((volatile unsigned*)&g_bar_gen) == gen) { }
        }
        __threadfence();
    }
    __syncthreads();
}

// ---------------------------------------------------------------------------
// Kernel 1: build normalized band adjacency (coalesced layout).
// g_band[i*BSTR + t], t = d + 191, t in [0,383). Row-normalized over the full
// 383-wide band (vs 4096 full row: error ~7e-8).
// ---------------------------------------------------------------------------
__global__ void __launch_bounds__(384) build_band_kernel(
    const int* __restrict__ spk, const float* __restrict__ mmask)
{
    int i = blockIdx.x;
    int t = threadIdx.x;            // 0..383, d = t - 191
    int d = t - 191;
    int j = i + d;

    float val = 0.0f;
    bool valid = (t < 383 && j >= 0 && j < NB);
    if (valid) {
        if (d == 0) {
            val = 1.0f;
        } else {
            float temporal = expf(-0.1f * fabsf((float)d));
            if (spk[i] == spk[j]) {
                val = 0.8f * temporal;
            } else {
                float md = fabsf(mmask[i*3+0] - mmask[j*3+0])
                         + fabsf(mmask[i*3+1] - mmask[j*3+1])
                         + fabsf(mmask[i*3+2] - mmask[j*3+2]);
                float mod_sim = 1.0f - md * (1.0f/3.0f);
                val = 0.5f * temporal * mod_sim;
            }
        }
    }

    __shared__ float sd[384];
    sd[t] = val;
    __syncthreads();
    // 384 = 256 + 128: fold the tail first, then power-of-2 reduction.
    if (t < 128) sd[t] += sd[t + 256];
    __syncthreads();
    for (int s = 128; s > 0; s >>= 1) {
        if (t < s) sd[t] += sd[t + s];
        __syncthreads();
    }
    float inv = 1.0f / (sd[0] + 1e-8f);
    g_band[i * BSTR + t] = val * inv;     // t=383 writes val=0 (harmless)
}

// ---------------------------------------------------------------------------
// Kernel 2: projection h0 = X @ Wp + bp.  512 threads, 4x2 microtile.
// ---------------------------------------------------------------------------
__global__ void __launch_bounds__(NT) proj_kernel(
    const float* __restrict__ X, const float* __restrict__ Wp,
    const float* __restrict__ bp)
{
    __shared__ __align__(16) float As[32 * SA];
    __shared__ __align__(16) float Bs[32 * 128];
    const int m0  = blockIdx.x * RPB;
    const int tid = threadIdx.x;
    const int rg  = tid >> 6;        // 0..7 -> rows 4rg..4rg+3 (warp-uniform)
    const int cg  = tid & 63;        // cols 2cg, 2cg+1

    ull acc[2][2];
    acc[0][0]=acc[0][1]=acc[1][0]=acc[1][1]=0ull;

    const int ar  = tid >> 4;        // 0..31
    const int ak2 = (tid & 15) * 2;  // 0..30

    for (int k0 = 0; k0 < DIN; k0 += 32) {
        {
            float2 v = *(const float2*)&X[(m0 + ar) * DIN + k0 + ak2];
            As[(ak2+0)*SA + ar] = v.x;
            As[(ak2+1)*SA + ar] = v.y;
        }
#pragma unroll
        for (int i = tid; i < 1024; i += NT) {
            int k = i >> 5, c4 = (i & 31) * 4;
            *(float4*)&Bs[k*128 + c4] = *(const float4*)&Wp[(k0 + k) * HH + c4];
        }
        __syncthreads();
#pragma unroll 8
        for (int k = 0; k < 32; k++)
            step4(acc, &As[k*SA + 4*rg], &Bs[k*128 + 2*cg]);
        __syncthreads();
    }

    float2 bb = *(const float2*)&bp[2*cg];
#pragma unroll
    for (int q = 0; q < 2; q++) {
        float2 f0 = unpk(acc[q][0]);
        float2 f1 = unpk(acc[q][1]);
        int r_even = m0 + 4*rg + 2*q;
        float2 o0 = make_float2(f0.x + bb.x, f1.x + bb.y);
        float2 o1 = make_float2(f0.y + bb.x, f1.y + bb.y);
        *(float2*)&g_h[r_even * HH + 2*cg]           = o0;
        *(float2*)&g_ybuf[0][r_even * HH + 2*cg]     = o0;
        *(float2*)&g_h[(r_even+1) * HH + 2*cg]       = o1;
        *(float2*)&g_ybuf[0][(r_even+1) * HH + 2*cg] = o1;
    }
}

// ---------------------------------------------------------------------------
// Kernel 3: persistent ODE kernel. 512 threads, W1 resident in smem.
// Matvec: smem-staged chunks with register double-buffer prefetch.
// W2 streamed via 8-deep register prefetch groups.
// ---------------------------------------------------------------------------
#define SW1_FLOATS (256 * 128)             // 32768
#define SY_FLOATS  (CH * 128)              // 6144
#define SB_FLOATS  (CH * 32)               // 1536
#define SCR_FLOATS (SY_FLOATS + SB_FLOATS) // 7680 (>= 128*SA = 4608, aliased)
#define SYT_FLOATS (128 * SA)              // 4608
#define SMEM_FLOATS (SW1_FLOATS + SCR_FLOATS + SYT_FLOATS)
#define SMEM_BYTES  (SMEM_FLOATS * 4)      // 180,224 B

__global__ void __launch_bounds__(NT, 1) ode_kernel(
    const float* __restrict__ W1, const float* __restrict__ b1,
    const float* __restrict__ W2, const float* __restrict__ b2,
    float* __restrict__ outp)
{
    extern __shared__ __align__(16) float smem[];
    float* sW1 = smem;                     // [256][128]
    float* sY  = sW1 + SW1_FLOATS;         // [CH][128]     (matvec y chunk)
    float* sB  = sY  + SY_FLOATS;          // [CH][32]      (band slice)
    float* sAt = sY;                       // [128][SA]     hn^T / z^T (aliased)
    float* sYT = sY + SCR_FLOATS;          // [128][SA]     y^T own rows (persistent)

    const int tid = threadIdx.x;
    const int rg  = tid >> 6;              // warp-uniform, rows 4rg..4rg+3
    const int cg  = tid & 63;              // cols 2cg, 2cg+1
    const int r0  = blockIdx.x * RPB;
    const int jbase = r0 - WB2;

    // one-time staging: W1, y0^T
#pragma unroll
    for (int i = tid; i < SW1_FLOATS/4; i += NT)
        *(float4*)&sW1[i*4] = *(const float4*)&W1[i*4];
#pragma unroll
    for (int i = tid; i < 4096; i += NT) {
        int r = i >> 7, c = i & 127;
        sYT[c*SA + r] = g_ybuf[0][(r0 + r) * HH + c];
    }

    // persistent register state: rows 4rg..4rg+3, cols 2cg, 2cg+1
    float hreg[4][2], rk[4][2];
#pragma unroll
    for (int i = 0; i < 4; i++) {
        float2 v = *(const float2*)&g_h[(r0 + 4*rg + i) * HH + 2*cg];
        hreg[i][0] = v.x; hreg[i][1] = v.y;
    }
    float2 b1v = *(const float2*)&b1[2*cg];
    float2 b2v = *(const float2*)&b2[2*cg];
    const float dt = 0.25f;
    __syncthreads();

#pragma unroll 1
    for (int st = 0; st < 16; st++) {
        const int s = st & 3;
        const float* __restrict__ yin  = g_ybuf[st & 1];
        float* __restrict__       yout = g_ybuf[(st + 1) & 1];

        // ---- banded matvec with register-double-buffered staging ----
        ull macc[2][2];
        macc[0][0]=macc[0][1]=macc[1][0]=macc[1][1]=0ull;

        float4 py[3];                      // y prefetch: 3 float4/thread
        float  pb[3];                      // band prefetch: 3 floats/thread

        // prefetch chunk 0
        {
            const int j0 = jbase;
#pragma unroll
            for (int q = 0; q < 3; q++) {
                int i = tid + q*NT;
                int row = i >> 5, c4 = (i & 31) * 4;
                int gj = j0 + row;
                py[q] = make_float4(0.f,0.f,0.f,0.f);
                if ((unsigned)gj < (unsigned)NB)
                    py[q] = *(const float4*)&yin[gj * HH + c4];
            }
#pragma unroll
            for (int q = 0; q < 3; q++) {
                int i = tid + q*NT;
                int jj = i >> 5, r = i & 31;
                int gj = j0 + jj;
                int dd = gj - (r0 + r) + 191;
                pb[q] = 0.0f;
                if ((unsigned)dd < 384u && (unsigned)gj < (unsigned)NB)
                    pb[q] = g_band[(r0 + r) * BSTR + dd];
            }
        }

#pragma unroll 1
        for (int ch = 0; ch < NCH; ch++) {
            // commit prefetched chunk to smem
#pragma unroll
            for (int q = 0; q < 3; q++) {
                int i = tid + q*NT;
                int row = i >> 5, c4 = (i & 31) * 4;
                *(float4*)&sY[row * 128 + c4] = py[q];
            }
#pragma unroll
            for (int q = 0; q < 3; q++) {
                int i = tid + q*NT;
                int jj = i >> 5, r = i & 31;
                sB[jj * 32 + r] = pb[q];
            }
            __syncthreads();

            // prefetch next chunk while computing this one
            if (ch + 1 < NCH) {
                const int j0 = jbase + (ch + 1) * CH;
#pragma unroll
                for (int q = 0; q < 3; q++) {
                    int i = tid + q*NT;
                    int row = i >> 5, c4 = (i & 31) * 4;
                    int gj = j0 + row;
                    py[q] = make_float4(0.f,0.f,0.f,0.f);
                    if ((unsigned)gj < (unsigned)NB)
                        py[q] = *(const float4*)&yin[gj * HH + c4];
                }
#pragma unroll
                for (int q = 0; q < 3; q++) {
                    int i = tid + q*NT;
                    int jj = i >> 5, r = i & 31;
                    int gj = j0 + jj;
                    int dd = gj - (r0 + r) + 191;
                    pb[q] = 0.0f;
                    if ((unsigned)dd < 384u && (unsigned)gj < (unsigned)NB)
                        pb[q] = g_band[(r0 + r) * BSTR + dd];
                }
            }

#pragma unroll 8
            for (int j = 0; j < CH; j++)
                step4(macc, &sB[j*32 + 4*rg], &sY[j*128 + 2*cg]);
            __syncthreads();
        }

        // ---- stage hn^T into sAt (aliases matvec scratch; safe post-sync) ----
#pragma unroll
        for (int q = 0; q < 2; q++)
#pragma unroll
            for (int c = 0; c < 2; c++) {
                float2 f = unpk(macc[q][c]);
                int col = 2*cg + c;
                sAt[col*SA + 4*rg + 2*q]     = f.x;
                sAt[col*SA + 4*rg + 2*q + 1] = f.y;
            }
        __syncthreads();

        // ---- mlp1: [y | hn] @ W1 ----
        ull acc1[2][2];
        acc1[0][0]=acc1[0][1]=acc1[1][0]=acc1[1][1]=0ull;
#pragma unroll 8
        for (int k = 0; k < 128; k++)
            step4(acc1, &sYT[k*SA + 4*rg], &sW1[k*128 + 2*cg]);
#pragma unroll 8
        for (int k = 0; k < 128; k++)
            step4(acc1, &sAt[k*SA + 4*rg], &sW1[(128 + k)*128 + 2*cg]);
        __syncthreads();                   // all hn^T reads done

        // ---- z = tanh(acc1 + b1) -> z^T into sAt ----
#pragma unroll
        for (int q = 0; q < 2; q++)
#pragma unroll
            for (int c = 0; c < 2; c++) {
                float2 f = unpk(acc1[q][c]);
                float bb = c ? b1v.y : b1v.x;
                int col = 2*cg + c;
                sAt[col*SA + 4*rg + 2*q]     = tanhf(f.x + bb);
                sAt[col*SA + 4*rg + 2*q + 1] = tanhf(f.y + bb);
            }
        __syncthreads();

        // ---- mlp2: k = z @ W2 + b2  (W2 via 8-deep register prefetch) ----
        ull acc2[2][2];
        acc2[0][0]=acc2[0][1]=acc2[1][0]=acc2[1][1]=0ull;
#pragma unroll 1
        for (int g = 0; g < 16; g++) {
            float2 w[8];
#pragma unroll
            for (int j = 0; j < 8; j++)
                w[j] = *(const float2*)&W2[(g*8 + j)*128 + 2*cg];
#pragma unroll
            for (int j = 0; j < 8; j++)
                step4v(acc2, &sAt[(g*8 + j)*SA + 4*rg], w[j]);
        }

        // ---- RK4 epilogue ----
        {
            const float wq = (s == 0 || s == 3) ? dt * (1.0f/6.0f) : dt * (1.0f/3.0f);
            const float cq = (s == 2) ? dt : 0.5f * dt;
            float kvals[4][2];
#pragma unroll
            for (int q = 0; q < 2; q++)
#pragma unroll
                for (int c = 0; c < 2; c++) {
                    float2 f = unpk(acc2[q][c]);
                    float bb = c ? b2v.y : b2v.x;
                    kvals[2*q][c]   = f.x + bb;
                    kvals[2*q+1][c] = f.y + bb;
                }
            float yn[4][2];
#pragma unroll
            for (int i = 0; i < 4; i++)
#pragma unroll
                for (int c = 0; c < 2; c++) {
                    float kv = kvals[i][c];
                    if (s == 0) rk[i][c] = hreg[i][c] + wq * kv;
                    else        rk[i][c] += wq * kv;
                    if (s == 3) { hreg[i][c] = rk[i][c]; yn[i][c] = rk[i][c]; }
                    else        yn[i][c] = hreg[i][c] + cq * kv;
                }
            // y to global (neighbors) and y^T to smem (own mlp1 next stage)
#pragma unroll
            for (int i = 0; i < 4; i++) {
                int row = 4*rg + i;
                int idx = (r0 + row) * HH + 2*cg;
                float2 o = make_float2(yn[i][0], yn[i][1]);
                *(float2*)&yout[idx] = o;
                sYT[(2*cg+0)*SA + row] = yn[i][0];
                sYT[(2*cg+1)*SA + row] = yn[i][1];
                if (st == 15) *(float2*)&outp[idx] = o;
            }
        }

        grid_sync_dev();
    }
}

// ---------------------------------------------------------------------------
extern "C" void kernel_launch(void* const* d_in, const int* in_sizes, int n_in,
                              void* d_out, int out_size)
{
    (void)in_sizes; (void)n_in; (void)out_size;
    const float* features = (const float*)d_in[0];
    const int*   spk      = (const int*)  d_in[1];
    const float* mmask    = (const float*)d_in[2];
    const float* Wp       = (const float*)d_in[3];
    const float* bp       = (const float*)d_in[4];
    const float* W1       = (const float*)d_in[5];
    const float* b1       = (const float*)d_in[6];
    const float* W2       = (const float*)d_in[7];
    const float* b2       = (const float*)d_in[8];
    float* out = (float*)d_out;

    static int attr_done = 0;
    if (!attr_done) {
        cudaFuncSetAttribute(ode_kernel,
                             cudaFuncAttributeMaxDynamicSharedMemorySize,
                             SMEM_BYTES);
        attr_done = 1;
    }

    build_band_kernel<<<NB, 384>>>(spk, mmask);
    proj_kernel<<<GRID, NT>>>(features, Wp, bp);
    ode_kernel<<<GRID, NT, SMEM_BYTES>>>(W1, b1, W2, b2, out);
}

// round 14
// speedup vs baseline: 1.8290x; 1.1677x over previous
#include <cuda_runtime.h>

// Problem constants
#define NB   4096
#define DIN  1856
#define HH   128
#define WB2  96        // truncated half-width (tail damped by RK4 dt-coeffs; ~1e-7 end-to-end)
#define BSTR 384       // band row stride (t = d+191)
#define GRID 128       // persistent blocks, all co-resident
#define RPB  32        // rows per block
#define CH   48        // matvec chunk rows
#define NCH  5         // 5*48 = 240 >= 2*96+32
#define SA   36        // transposed-activation stride
#define NT   512       // threads per block

typedef unsigned long long ull;

// Persistent device scratch (zero-initialized at module load)
__device__ float g_band[NB * BSTR];
__device__ float g_h[NB * HH];
__device__ float g_ybuf[2][NB * HH];
__device__ int g_done[GRID];          // per-block stage flags (reset by proj)

// ---------------------------------------------------------------------------
// f32x2 packed-math helpers
// ---------------------------------------------------------------------------
__device__ __forceinline__ ull dup2(float x) {
    ull r; asm("mov.b64 %0, {%1, %1};" : "=l"(r) : "f"(x)); return r;
}
__device__ __forceinline__ void ffma2(ull& d, ull a, ull b) {
    asm("fma.rn.f32x2 %0, %1, %2, %0;" : "+l"(d) : "l"(a), "l"(b));
}
__device__ __forceinline__ float2 unpk(ull v) {
    float2 f; asm("mov.b64 {%0, %1}, %2;" : "=f"(f.x), "=f"(f.y) : "l"(v));
    return f;
}

// 4 rows x 2 cols microtile: 1 LDS.128 (row pairs) + 1 LDS.64 (cols).
__device__ __forceinline__ void step4(ull acc[2][2],
                                      const float* __restrict__ aBase,
                                      const float* __restrict__ bBase)
{
    ulonglong2 a = *(const ulonglong2*)(aBase);        // rows (0,1),(2,3)
    float2 wv = *(const float2*)(bBase);
    ull w0 = dup2(wv.x), w1 = dup2(wv.y);
    ffma2(acc[0][0], a.x, w0); ffma2(acc[0][1], a.x, w1);
    ffma2(acc[1][0], a.y, w0); ffma2(acc[1][1], a.y, w1);
}
__device__ __forceinline__ void step4v(ull acc[2][2],
                                       const float* __restrict__ aBase,
                                       float2 wv)
{
    ulonglong2 a = *(const ulonglong2*)(aBase);
    ull w0 = dup2(wv.x), w1 = dup2(wv.y);
    ffma2(acc[0][0], a.x, w0); ffma2(acc[0][1], a.x, w1);
    ffma2(acc[1][0], a.y, w0); ffma2(acc[1][1], a.y, w1);
}

// ---------------------------------------------------------------------------
// Kernel 1: build normalized band adjacency (coalesced layout).
// Normalizer over the full 383-wide band (error vs full row ~7e-8).
// ---------------------------------------------------------------------------
__global__ void __launch_bounds__(384) build_band_kernel(
    const int* __restrict__ spk, const float* __restrict__ mmask)
{
    int i = blockIdx.x;
    int t = threadIdx.x;            // 0..383, d = t - 191
    int d = t - 191;
    int j = i + d;

    float val = 0.0f;
    bool valid = (t < 383 && j >= 0 && j < NB);
    if (valid) {
        if (d == 0) {
            val = 1.0f;
        } else {
            float temporal = expf(-0.1f * fabsf((float)d));
            if (spk[i] == spk[j]) {
                val = 0.8f * temporal;
            } else {
                float md = fabsf(mmask[i*3+0] - mmask[j*3+0])
                         + fabsf(mmask[i*3+1] - mmask[j*3+1])
                         + fabsf(mmask[i*3+2] - mmask[j*3+2]);
                float mod_sim = 1.0f - md * (1.0f/3.0f);
                val = 0.5f * temporal * mod_sim;
            }
        }
    }

    __shared__ float sd[384];
    sd[t] = val;
    __syncthreads();
    if (t < 128) sd[t] += sd[t + 256];
    __syncthreads();
    for (int s = 128; s > 0; s >>= 1) {
        if (t < s) sd[t] += sd[t + s];
        __syncthreads();
    }
    float inv = 1.0f / (sd[0] + 1e-8f);
    g_band[i * BSTR + t] = val * inv;
}

// ---------------------------------------------------------------------------
// Kernel 2: projection h0 = X @ Wp + bp.  Also resets g_done for this launch.
// ---------------------------------------------------------------------------
__global__ void __launch_bounds__(NT) proj_kernel(
    const float* __restrict__ X, const float* __restrict__ Wp,
    const float* __restrict__ bp)
{
    if (threadIdx.x == 0) g_done[blockIdx.x] = 0;     // flag reset (per launch)

    __shared__ __align__(16) float As[32 * SA];
    __shared__ __align__(16) float Bs[32 * 128];
    const int m0  = blockIdx.x * RPB;
    const int tid = threadIdx.x;
    const int rg  = tid >> 6;        // 0..7 -> rows 4rg..4rg+3 (warp-uniform)
    const int cg  = tid & 63;        // cols 2cg, 2cg+1

    ull acc[2][2];
    acc[0][0]=acc[0][1]=acc[1][0]=acc[1][1]=0ull;

    const int ar  = tid >> 4;        // 0..31
    const int ak2 = (tid & 15) * 2;  // 0..30

    for (int k0 = 0; k0 < DIN; k0 += 32) {
        {
            float2 v = *(const float2*)&X[(m0 + ar) * DIN + k0 + ak2];
            As[(ak2+0)*SA + ar] = v.x;
            As[(ak2+1)*SA + ar] = v.y;
        }
#pragma unroll
        for (int i = tid; i < 1024; i += NT) {
            int k = i >> 5, c4 = (i & 31) * 4;
            *(float4*)&Bs[k*128 + c4] = *(const float4*)&Wp[(k0 + k) * HH + c4];
        }
        __syncthreads();
#pragma unroll 8
        for (int k = 0; k < 32; k++)
            step4(acc, &As[k*SA + 4*rg], &Bs[k*128 + 2*cg]);
        __syncthreads();
    }

    float2 bb = *(const float2*)&bp[2*cg];
#pragma unroll
    for (int q = 0; q < 2; q++) {
        float2 f0 = unpk(acc[q][0]);
        float2 f1 = unpk(acc[q][1]);
        int r_even = m0 + 4*rg + 2*q;
        float2 o0 = make_float2(f0.x + bb.x, f1.x + bb.y);
        float2 o1 = make_float2(f0.y + bb.x, f1.y + bb.y);
        *(float2*)&g_h[r_even * HH + 2*cg]           = o0;
        *(float2*)&g_ybuf[0][r_even * HH + 2*cg]     = o0;
        *(float2*)&g_h[(r_even+1) * HH + 2*cg]       = o1;
        *(float2*)&g_ybuf[0][(r_even+1) * HH + 2*cg] = o1;
    }
}

// ---------------------------------------------------------------------------
// Kernel 3: persistent ODE kernel.
// Neighbor-only dataflow sync (blocks +-3), double-buffered matvec staging,
// W1 resident in smem, W2 via 8-deep register prefetch.
// ---------------------------------------------------------------------------
#define SW1_FLOATS (256 * 128)             // 32768
#define SY_FLOATS  (CH * 128)              // 6144
#define SB_FLOATS  (CH * 32)               // 1536
#define SYT_FLOATS (128 * SA)              // 4608
#define SMEM_FLOATS (SW1_FLOATS + 2*SY_FLOATS + 2*SB_FLOATS + SYT_FLOATS)
#define SMEM_BYTES  (SMEM_FLOATS * 4)      // 210944 B

__global__ void __launch_bounds__(NT, 1) ode_kernel(
    const float* __restrict__ W1, const float* __restrict__ b1,
    const float* __restrict__ W2, const float* __restrict__ b2,
    float* __restrict__ outp)
{
    extern __shared__ __align__(16) float smem[];
    float* sW1 = smem;                     // [256][128]
    float* sY0 = sW1 + SW1_FLOATS;         // [CH][128] buffer 0
    float* sY1 = sY0 + SY_FLOATS;          // [CH][128] buffer 1
    float* sB0 = sY1 + SY_FLOATS;          // [CH][32]  buffer 0
    float* sB1 = sB0 + SB_FLOATS;          // [CH][32]  buffer 1
    float* sYT = sB1 + SB_FLOATS;          // [128][SA] y^T own rows (persistent)
    float* sAt = sY0;                      // [128][SA] hn^T / z^T (aliases sY0)

    const int tid = threadIdx.x;
    const int rg  = tid >> 6;              // warp-uniform, rows 4rg..4rg+3
    const int cg  = tid & 63;              // cols 2cg, 2cg+1
    const int r0  = blockIdx.x * RPB;
    const int jbase = r0 - WB2;

    // one-time staging: W1, y0^T
#pragma unroll
    for (int i = tid; i < SW1_FLOATS/4; i += NT)
        *(float4*)&sW1[i*4] = *(const float4*)&W1[i*4];
#pragma unroll
    for (int i = tid; i < 4096; i += NT) {
        int r = i >> 7, c = i & 127;
        sYT[c*SA + r] = g_ybuf[0][(r0 + r) * HH + c];
    }

    // persistent register state: rows 4rg..4rg+3, cols 2cg, 2cg+1
    float hreg[4][2], rk[4][2];
#pragma unroll
    for (int i = 0; i < 4; i++) {
        float2 v = *(const float2*)&g_h[(r0 + 4*rg + i) * HH + 2*cg];
        hreg[i][0] = v.x; hreg[i][1] = v.y;
    }
    float2 b1v = *(const float2*)&b1[2*cg];
    float2 b2v = *(const float2*)&b2[2*cg];
    const float dt = 0.25f;
    __syncthreads();

#pragma unroll 1
    for (int st = 0; st < 16; st++) {
        const int s = st & 3;
        const float* __restrict__ yin  = g_ybuf[st & 1];
        float* __restrict__       yout = g_ybuf[(st + 1) & 1];

        // ---- neighbor dataflow sync: wait for blocks +-3 to publish yin ----
        if (st > 0) {
            if (tid < 7) {
                int nb = (int)blockIdx.x - 3 + tid;
                if (nb >= 0 && nb < GRID) {
                    while (((volatile int*)g_done)[nb] < st) { }
                }
            }
            __syncthreads();
            __threadfence();
        }

        // ---- banded matvec with smem double-buffered staging ----
        ull macc[2][2];
        macc[0][0]=macc[0][1]=macc[1][0]=macc[1][1]=0ull;

        float4 py[3];
        float  pb[3];

        // prefetch + commit chunk 0 into buffer 0
        {
            const int j0 = jbase;
#pragma unroll
            for (int q = 0; q < 3; q++) {
                int i = tid + q*NT;
                int row = i >> 5, c4 = (i & 31) * 4;
                int gj = j0 + row;
                py[q] = make_float4(0.f,0.f,0.f,0.f);
                if ((unsigned)gj < (unsigned)NB)
                    py[q] = __ldcg((const float4*)&yin[gj * HH + c4]);
                *(float4*)&sY0[row * 128 + c4] = py[q];
            }
#pragma unroll
            for (int q = 0; q < 3; q++) {
                int i = tid + q*NT;
                int jj = i >> 5, r = i & 31;
                int gj = j0 + jj;
                int dd = gj - (r0 + r) + 191;
                pb[q] = 0.0f;
                if ((unsigned)dd < 384u && (unsigned)gj < (unsigned)NB)
                    pb[q] = g_band[(r0 + r) * BSTR + dd];
                sB0[jj * 32 + r] = pb[q];
            }
        }

#pragma unroll 1
        for (int ch = 0; ch < NCH; ch++) {
            __syncthreads();               // current buffer ready
            const float* cY = (ch & 1) ? sY1 : sY0;
            const float* cB = (ch & 1) ? sB1 : sB0;
            float* nY = (ch & 1) ? sY0 : sY1;
            float* nB = (ch & 1) ? sB0 : sB1;

            // issue next chunk's loads (latency overlapped with compute)
            if (ch + 1 < NCH) {
                const int j0 = jbase + (ch + 1) * CH;
#pragma unroll
                for (int q = 0; q < 3; q++) {
                    int i = tid + q*NT;
                    int row = i >> 5, c4 = (i & 31) * 4;
                    int gj = j0 + row;
                    py[q] = make_float4(0.f,0.f,0.f,0.f);
                    if ((unsigned)gj < (unsigned)NB)
                        py[q] = __ldcg((const float4*)&yin[gj * HH + c4]);
                }
#pragma unroll
                for (int q = 0; q < 3; q++) {
                    int i = tid + q*NT;
                    int jj = i >> 5, r = i & 31;
                    int gj = j0 + jj;
                    int dd = gj - (r0 + r) + 191;
                    pb[q] = 0.0f;
                    if ((unsigned)dd < 384u && (unsigned)gj < (unsigned)NB)
                        pb[q] = g_band[(r0 + r) * BSTR + dd];
                }
            }

#pragma unroll 8
            for (int j = 0; j < CH; j++)
                step4(macc, &cB[j*32 + 4*rg], &cY[j*128 + 2*cg]);

            // commit prefetched chunk to the other buffer
            if (ch + 1 < NCH) {
#pragma unroll
                for (int q = 0; q < 3; q++) {
                    int i = tid + q*NT;
                    int row = i >> 5, c4 = (i & 31) * 4;
                    *(float4*)&nY[row * 128 + c4] = py[q];
                }
#pragma unroll
                for (int q = 0; q < 3; q++) {
                    int i = tid + q*NT;
                    int jj = i >> 5, r = i & 31;
                    nB[jj * 32 + r] = pb[q];
                }
            }
        }
        __syncthreads();                   // all matvec compute done (sAt aliases sY0)

        // ---- stage hn^T into sAt ----
#pragma unroll
        for (int q = 0; q < 2; q++)
#pragma unroll
            for (int c = 0; c < 2; c++) {
                float2 f = unpk(macc[q][c]);
                int col = 2*cg + c;
                sAt[col*SA + 4*rg + 2*q]     = f.x;
                sAt[col*SA + 4*rg + 2*q + 1] = f.y;
            }
        __syncthreads();

        // ---- mlp1: [y | hn] @ W1 ----
        ull acc1[2][2];
        acc1[0][0]=acc1[0][1]=acc1[1][0]=acc1[1][1]=0ull;
#pragma unroll 8
        for (int k = 0; k < 128; k++)
            step4(acc1, &sYT[k*SA + 4*rg], &sW1[k*128 + 2*cg]);
#pragma unroll 8
        for (int k = 0; k < 128; k++)
            step4(acc1, &sAt[k*SA + 4*rg], &sW1[(128 + k)*128 + 2*cg]);
        __syncthreads();                   // all hn^T reads done

        // ---- z = tanh(acc1 + b1) -> z^T into sAt ----
#pragma unroll
        for (int q = 0; q < 2; q++)
#pragma unroll
            for (int c = 0; c < 2; c++) {
                float2 f = unpk(acc1[q][c]);
                float bb = c ? b1v.y : b1v.x;
                int col = 2*cg + c;
                sAt[col*SA + 4*rg + 2*q]     = tanhf(f.x + bb);
                sAt[col*SA + 4*rg + 2*q + 1] = tanhf(f.y + bb);
            }
        __syncthreads();

        // ---- mlp2: k = z @ W2 + b2  (W2 via 8-deep register prefetch) ----
        ull acc2[2][2];
        acc2[0][0]=acc2[0][1]=acc2[1][0]=acc2[1][1]=0ull;
#pragma unroll 1
        for (int g = 0; g < 16; g++) {
            float2 w[8];
#pragma unroll
            for (int j = 0; j < 8; j++)
                w[j] = *(const float2*)&W2[(g*8 + j)*128 + 2*cg];
#pragma unroll
            for (int j = 0; j < 8; j++)
                step4v(acc2, &sAt[(g*8 + j)*SA + 4*rg], w[j]);
        }

        // ---- RK4 epilogue ----
        {
            const float wq = (s == 0 || s == 3) ? dt * (1.0f/6.0f) : dt * (1.0f/3.0f);
            const float cq = (s == 2) ? dt : 0.5f * dt;
            float kvals[4][2];
#pragma unroll
            for (int q = 0; q < 2; q++)
#pragma unroll
                for (int c = 0; c < 2; c++) {
                    float2 f = unpk(acc2[q][c]);
                    float bb = c ? b2v.y : b2v.x;
                    kvals[2*q][c]   = f.x + bb;
                    kvals[2*q+1][c] = f.y + bb;
                }
            float yn[4][2];
#pragma unroll
            for (int i = 0; i < 4; i++)
#pragma unroll
                for (int c = 0; c < 2; c++) {
                    float kv = kvals[i][c];
                    if (s == 0) rk[i][c] = hreg[i][c] + wq * kv;
                    else        rk[i][c] += wq * kv;
                    if (s == 3) { hreg[i][c] = rk[i][c]; yn[i][c] = rk[i][c]; }
                    else        yn[i][c] = hreg[i][c] + cq * kv;
                }
#pragma unroll
            for (int i = 0; i < 4; i++) {
                int row = 4*rg + i;
                int idx = (r0 + row) * HH + 2*cg;
                float2 o = make_float2(yn[i][0], yn[i][1]);
                *(float2*)&yout[idx] = o;
                sYT[(2*cg+0)*SA + row] = yn[i][0];
                sYT[(2*cg+1)*SA + row] = yn[i][1];
                if (st == 15) *(float2*)&outp[idx] = o;
            }
        }

        // ---- publish stage completion for neighbors ----
        if (st < 15) {
            __syncthreads();               // all yout stores issued block-wide
            if (tid == 0) {
                __threadfence();           // yout visible before flag
                atomicExch(&g_done[blockIdx.x], st + 1);
            }
        }
    }
}

// ---------------------------------------------------------------------------
extern "C" void kernel_launch(void* const* d_in, const int* in_sizes, int n_in,
                              void* d_out, int out_size)
{
    (void)in_sizes; (void)n_in; (void)out_size;
    const float* features = (const float*)d_in[0];
    const int*   spk      = (const int*)  d_in[1];
    const float* mmask    = (const float*)d_in[2];
    const float* Wp       = (const float*)d_in[3];
    const float* bp       = (const float*)d_in[4];
    const float* W1       = (const float*)d_in[5];
    const float* b1       = (const float*)d_in[6];
    const float* W2       = (const float*)d_in[7];
    const float* b2       = (const float*)d_in[8];
    float* out = (float*)d_out;

    static int attr_done = 0;
    if (!attr_done) {
        cudaFuncSetAttribute(ode_kernel,
                             cudaFuncAttributeMaxDynamicSharedMemorySize,
                             SMEM_BYTES);
        attr_done = 1;
    }

    build_band_kernel<<<NB, 384>>>(spk, mmask);
    proj_kernel<<<GRID, NT>>>(features, Wp, bp);
    ode_kernel<<<GRID, NT, SMEM_BYTES>>>(W1, b1, W2, b2, out);
}

// round 15
// speedup vs baseline: 1.9185x; 1.0489x over previous
#include <cuda_runtime.h>

// Problem constants
#define NB   4096
#define DIN  1856
#define HH   128
#define WB2  96        // truncated half-width (window covers >= +-96 per row)
#define BSTR 384       // band row stride (t = d+191)
#define GRID 128       // persistent blocks, all co-resident
#define RPB  32        // rows per block
#define CH   48        // matvec chunk rows
#define NCH  5         // 5*48 = 240 window cols
#define NJW  (NCH*CH)  // 240
#define SA   36        // transposed-activation stride
#define NT   512       // threads per block

typedef unsigned long long ull;

// Persistent device scratch (zero-initialized at module load)
__device__ float g_band[NB * BSTR];
__device__ float g_h[NB * HH];
__device__ float g_ybuf[2][NB * HH];
__device__ int g_done[GRID];          // per-block stage flags (reset by proj)

// ---------------------------------------------------------------------------
// f32x2 packed-math helpers
// ---------------------------------------------------------------------------
__device__ __forceinline__ ull dup2(float x) {
    ull r; asm("mov.b64 %0, {%1, %1};" : "=l"(r) : "f"(x)); return r;
}
__device__ __forceinline__ void ffma2(ull& d, ull a, ull b) {
    asm("fma.rn.f32x2 %0, %1, %2, %0;" : "+l"(d) : "l"(a), "l"(b));
}
__device__ __forceinline__ float2 unpk(ull v) {
    float2 f; asm("mov.b64 {%0, %1}, %2;" : "=f"(f.x), "=f"(f.y) : "l"(v));
    return f;
}

// 4 rows x 2 cols microtile: 1 LDS.128 (row pairs) + 1 LDS.64 (cols).
__device__ __forceinline__ void step4(ull acc[2][2],
                                      const float* __restrict__ aBase,
                                      const float* __restrict__ bBase)
{
    ulonglong2 a = *(const ulonglong2*)(aBase);        // rows (0,1),(2,3)
    float2 wv = *(const float2*)(bBase);
    ull w0 = dup2(wv.x), w1 = dup2(wv.y);
    ffma2(acc[0][0], a.x, w0); ffma2(acc[0][1], a.x, w1);
    ffma2(acc[1][0], a.y, w0); ffma2(acc[1][1], a.y, w1);
}
__device__ __forceinline__ void step4v(ull acc[2][2],
                                       const float* __restrict__ aBase,
                                       float2 wv)
{
    ulonglong2 a = *(const ulonglong2*)(aBase);
    ull w0 = dup2(wv.x), w1 = dup2(wv.y);
    ffma2(acc[0][0], a.x, w0); ffma2(acc[0][1], a.x, w1);
    ffma2(acc[1][0], a.y, w0); ffma2(acc[1][1], a.y, w1);
}

// ---------------------------------------------------------------------------
// Kernel 1: build normalized band adjacency (coalesced layout).
// Normalizer over the full 383-wide band (error vs full row ~7e-8).
// ---------------------------------------------------------------------------
__global__ void __launch_bounds__(384) build_band_kernel(
    const int* __restrict__ spk, const float* __restrict__ mmask)
{
    int i = blockIdx.x;
    int t = threadIdx.x;            // 0..383, d = t - 191
    int d = t - 191;
    int j = i + d;

    float val = 0.0f;
    bool valid = (t < 383 && j >= 0 && j < NB);
    if (valid) {
        if (d == 0) {
            val = 1.0f;
        } else {
            float temporal = expf(-0.1f * fabsf((float)d));
            if (spk[i] == spk[j]) {
                val = 0.8f * temporal;
            } else {
                float md = fabsf(mmask[i*3+0] - mmask[j*3+0])
                         + fabsf(mmask[i*3+1] - mmask[j*3+1])
                         + fabsf(mmask[i*3+2] - mmask[j*3+2]);
                float mod_sim = 1.0f - md * (1.0f/3.0f);
                val = 0.5f * temporal * mod_sim;
            }
        }
    }

    __shared__ float sd[384];
    sd[t] = val;
    __syncthreads();
    if (t < 128) sd[t] += sd[t + 256];
    __syncthreads();
    for (int s = 128; s > 0; s >>= 1) {
        if (t < s) sd[t] += sd[t + s];
        __syncthreads();
    }
    float inv = 1.0f / (sd[0] + 1e-8f);
    g_band[i * BSTR + t] = val * inv;
}

// ---------------------------------------------------------------------------
// Kernel 2: projection h0 = X @ Wp + bp.  Also resets g_done for this launch.
// ---------------------------------------------------------------------------
__global__ void __launch_bounds__(NT) proj_kernel(
    const float* __restrict__ X, const float* __restrict__ Wp,
    const float* __restrict__ bp)
{
    if (threadIdx.x == 0) g_done[blockIdx.x] = 0;     // flag reset (per launch)

    __shared__ __align__(16) float As[32 * SA];
    __shared__ __align__(16) float Bs[32 * 128];
    const int m0  = blockIdx.x * RPB;
    const int tid = threadIdx.x;
    const int rg  = tid >> 6;        // 0..7 -> rows 4rg..4rg+3 (warp-uniform)
    const int cg  = tid & 63;        // cols 2cg, 2cg+1

    ull acc[2][2];
    acc[0][0]=acc[0][1]=acc[1][0]=acc[1][1]=0ull;

    const int ar  = tid >> 4;        // 0..31
    const int ak2 = (tid & 15) * 2;  // 0..30

    for (int k0 = 0; k0 < DIN; k0 += 32) {
        {
            float2 v = *(const float2*)&X[(m0 + ar) * DIN + k0 + ak2];
            As[(ak2+0)*SA + ar] = v.x;
            As[(ak2+1)*SA + ar] = v.y;
        }
#pragma unroll
        for (int i = tid; i < 1024; i += NT) {
            int k = i >> 5, c4 = (i & 31) * 4;
            *(float4*)&Bs[k*128 + c4] = *(const float4*)&Wp[(k0 + k) * HH + c4];
        }
        __syncthreads();
#pragma unroll 8
        for (int k = 0; k < 32; k++)
            step4(acc, &As[k*SA + 4*rg], &Bs[k*128 + 2*cg]);
        __syncthreads();
    }

    float2 bb = *(const float2*)&bp[2*cg];
#pragma unroll
    for (int q = 0; q < 2; q++) {
        float2 f0 = unpk(acc[q][0]);
        float2 f1 = unpk(acc[q][1]);
        int r_even = m0 + 4*rg + 2*q;
        float2 o0 = make_float2(f0.x + bb.x, f1.x + bb.y);
        float2 o1 = make_float2(f0.y + bb.x, f1.y + bb.y);
        *(float2*)&g_h[r_even * HH + 2*cg]           = o0;
        *(float2*)&g_ybuf[0][r_even * HH + 2*cg]     = o0;
        *(float2*)&g_h[(r_even+1) * HH + 2*cg]       = o1;
        *(float2*)&g_ybuf[0][(r_even+1) * HH + 2*cg] = o1;
    }
}

// ---------------------------------------------------------------------------
// Kernel 3: persistent ODE kernel.
// Band slice resident in smem for all 16 stages (stage-invariant!).
// Neighbor-only dataflow sync, y-only double-buffered staging,
// W1 resident in smem, W2 via 8-deep register prefetch.
// ---------------------------------------------------------------------------
#define SW1_FLOATS (256 * 128)             // 32768
#define SY_FLOATS  (CH * 128)              // 6144
#define SBT_FLOATS (NJW * 32)              // 7680
#define SYT_FLOATS (128 * SA)              // 4608
#define SMEM_FLOATS (SW1_FLOATS + 2*SY_FLOATS + SBT_FLOATS + SYT_FLOATS)
#define SMEM_BYTES  (SMEM_FLOATS * 4)      // 229376 B (fits 232448 cap)

__global__ void __launch_bounds__(NT, 1) ode_kernel(
    const float* __restrict__ W1, const float* __restrict__ b1,
    const float* __restrict__ W2, const float* __restrict__ b2,
    float* __restrict__ outp)
{
    extern __shared__ __align__(16) float smem[];
    float* sW1 = smem;                     // [256][128]
    float* sY0 = sW1 + SW1_FLOATS;         // [CH][128] buffer 0
    float* sY1 = sY0 + SY_FLOATS;          // [CH][128] buffer 1
    float* sBT = sY1 + SY_FLOATS;          // [NJW][32] resident band slice
    float* sYT = sBT + SBT_FLOATS;         // [128][SA] y^T own rows (persistent)
    float* sAt = sY0;                      // [128][SA] hn^T / z^T (aliases sY0)

    const int tid = threadIdx.x;
    const int rg  = tid >> 6;              // warp-uniform, rows 4rg..4rg+3
    const int cg  = tid & 63;              // cols 2cg, 2cg+1
    const int r0  = blockIdx.x * RPB;
    const int jbase = r0 - WB2;

    // one-time staging: W1, band slice (transposed [jj][r]), y0^T
#pragma unroll
    for (int i = tid; i < SW1_FLOATS/4; i += NT)
        *(float4*)&sW1[i*4] = *(const float4*)&W1[i*4];
#pragma unroll
    for (int i = tid; i < SBT_FLOATS; i += NT) {
        int jj = i >> 5, r = i & 31;
        int gj = jbase + jj;
        float bv = 0.0f;
        if ((unsigned)gj < (unsigned)NB) {
            int dd = jj + 95 - r;          // in [64, 334] always
            bv = g_band[(r0 + r) * BSTR + dd];
        }
        sBT[i] = bv;
    }
#pragma unroll
    for (int i = tid; i < 4096; i += NT) {
        int r = i >> 7, c = i & 127;
        sYT[c*SA + r] = g_ybuf[0][(r0 + r) * HH + c];
    }

    // persistent register state: rows 4rg..4rg+3, cols 2cg, 2cg+1
    float hreg[4][2], rk[4][2];
#pragma unroll
    for (int i = 0; i < 4; i++) {
        float2 v = *(const float2*)&g_h[(r0 + 4*rg + i) * HH + 2*cg];
        hreg[i][0] = v.x; hreg[i][1] = v.y;
    }
    float2 b1v = *(const float2*)&b1[2*cg];
    float2 b2v = *(const float2*)&b2[2*cg];
    const float dt = 0.25f;
    __syncthreads();

#pragma unroll 1
    for (int st = 0; st < 16; st++) {
        const int s = st & 3;
        const float* __restrict__ yin  = g_ybuf[st & 1];
        float* __restrict__       yout = g_ybuf[(st + 1) & 1];

        // ---- neighbor dataflow sync: wait for blocks +-3 to publish yin ----
        if (st > 0) {
            if (tid < 7) {
                int nb = (int)blockIdx.x - 3 + tid;
                if (nb >= 0 && nb < GRID) {
                    while (((volatile int*)g_done)[nb] < st) { }
                }
            }
            __syncthreads();
            __threadfence();
        }

        // ---- banded matvec: y double-buffered, band resident ----
        ull macc[2][2];
        macc[0][0]=macc[0][1]=macc[1][0]=macc[1][1]=0ull;

        float4 py[3];

        // prefetch + commit chunk 0 into buffer 0
        {
#pragma unroll
            for (int q = 0; q < 3; q++) {
                int i = tid + q*NT;
                int row = i >> 5, c4 = (i & 31) * 4;
                int gj = jbase + row;
                py[q] = make_float4(0.f,0.f,0.f,0.f);
                if ((unsigned)gj < (unsigned)NB)
                    py[q] = __ldcg((const float4*)&yin[gj * HH + c4]);
                *(float4*)&sY0[row * 128 + c4] = py[q];
            }
        }

#pragma unroll 1
        for (int ch = 0; ch < NCH; ch++) {
            __syncthreads();               // current buffer ready
            const float* cY = (ch & 1) ? sY1 : sY0;
            float* nY = (ch & 1) ? sY0 : sY1;
            const float* cB = &sBT[ch * CH * 32];

            // issue next chunk's y loads (latency overlapped with compute)
            if (ch + 1 < NCH) {
                const int j0 = jbase + (ch + 1) * CH;
#pragma unroll
                for (int q = 0; q < 3; q++) {
                    int i = tid + q*NT;
                    int row = i >> 5, c4 = (i & 31) * 4;
                    int gj = j0 + row;
                    py[q] = make_float4(0.f,0.f,0.f,0.f);
                    if ((unsigned)gj < (unsigned)NB)
                        py[q] = __ldcg((const float4*)&yin[gj * HH + c4]);
                }
            }

#pragma unroll 8
            for (int j = 0; j < CH; j++)
                step4(macc, &cB[j*32 + 4*rg], &cY[j*128 + 2*cg]);

            // commit prefetched chunk to the other buffer
            if (ch + 1 < NCH) {
#pragma unroll
                for (int q = 0; q < 3; q++) {
                    int i = tid + q*NT;
                    int row = i >> 5, c4 = (i & 31) * 4;
                    *(float4*)&nY[row * 128 + c4] = py[q];
                }
            }
        }
        __syncthreads();                   // all matvec compute done (sAt aliases sY0)

        // ---- stage hn^T into sAt ----
#pragma unroll
        for (int q = 0; q < 2; q++)
#pragma unroll
            for (int c = 0; c < 2; c++) {
                float2 f = unpk(macc[q][c]);
                int col = 2*cg + c;
                sAt[col*SA + 4*rg + 2*q]     = f.x;
                sAt[col*SA + 4*rg + 2*q + 1] = f.y;
            }
        __syncthreads();

        // ---- mlp1: [y | hn] @ W1 ----
        ull acc1[2][2];
        acc1[0][0]=acc1[0][1]=acc1[1][0]=acc1[1][1]=0ull;
#pragma unroll 8
        for (int k = 0; k < 128; k++)
            step4(acc1, &sYT[k*SA + 4*rg], &sW1[k*128 + 2*cg]);
#pragma unroll 8
        for (int k = 0; k < 128; k++)
            step4(acc1, &sAt[k*SA + 4*rg], &sW1[(128 + k)*128 + 2*cg]);
        __syncthreads();                   // all hn^T reads done

        // ---- z = tanh(acc1 + b1) -> z^T into sAt ----
#pragma unroll
        for (int q = 0; q < 2; q++)
#pragma unroll
            for (int c = 0; c < 2; c++) {
                float2 f = unpk(acc1[q][c]);
                float bb = c ? b1v.y : b1v.x;
                int col = 2*cg + c;
                sAt[col*SA + 4*rg + 2*q]     = tanhf(f.x + bb);
                sAt[col*SA + 4*rg + 2*q + 1] = tanhf(f.y + bb);
            }
        __syncthreads();

        // ---- mlp2: k = z @ W2 + b2  (W2 via 8-deep register prefetch) ----
        ull acc2[2][2];
        acc2[0][0]=acc2[0][1]=acc2[1][0]=acc2[1][1]=0ull;
#pragma unroll 1
        for (int g = 0; g < 16; g++) {
            float2 w[8];
#pragma unroll
            for (int j = 0; j < 8; j++)
                w[j] = *(const float2*)&W2[(g*8 + j)*128 + 2*cg];
#pragma unroll
            for (int j = 0; j < 8; j++)
                step4v(acc2, &sAt[(g*8 + j)*SA + 4*rg], w[j]);
        }

        // ---- RK4 epilogue ----
        {
            const float wq = (s == 0 || s == 3) ? dt * (1.0f/6.0f) : dt * (1.0f/3.0f);
            const float cq = (s == 2) ? dt : 0.5f * dt;
            float kvals[4][2];
#pragma unroll
            for (int q = 0; q < 2; q++)
#pragma unroll
                for (int c = 0; c < 2; c++) {
                    float2 f = unpk(acc2[q][c]);
                    float bb = c ? b2v.y : b2v.x;
                    kvals[2*q][c]   = f.x + bb;
                    kvals[2*q+1][c] = f.y + bb;
                }
            float yn[4][2];
#pragma unroll
            for (int i = 0; i < 4; i++)
#pragma unroll
                for (int c = 0; c < 2; c++) {
                    float kv = kvals[i][c];
                    if (s == 0) rk[i][c] = hreg[i][c] + wq * kv;
                    else        rk[i][c] += wq * kv;
                    if (s == 3) { hreg[i][c] = rk[i][c]; yn[i][c] = rk[i][c]; }
                    else        yn[i][c] = hreg[i][c] + cq * kv;
                }
#pragma unroll
            for (int i = 0; i < 4; i++) {
                int row = 4*rg + i;
                int idx = (r0 + row) * HH + 2*cg;
                float2 o = make_float2(yn[i][0], yn[i][1]);
                *(float2*)&yout[idx] = o;
                sYT[(2*cg+0)*SA + row] = yn[i][0];
                sYT[(2*cg+1)*SA + row] = yn[i][1];
                if (st == 15) *(float2*)&outp[idx] = o;
            }
        }

        // ---- publish stage completion for neighbors ----
        if (st < 15) {
            __syncthreads();               // all yout stores issued block-wide
            if (tid == 0) {
                __threadfence();           // yout visible before flag
                atomicExch(&g_done[blockIdx.x], st + 1);
            }
        }
    }
}

// ---------------------------------------------------------------------------
extern "C" void kernel_launch(void* const* d_in, const int* in_sizes, int n_in,
                              void* d_out, int out_size)
{
    (void)in_sizes; (void)n_in; (void)out_size;
    const float* features = (const float*)d_in[0];
    const int*   spk      = (const int*)  d_in[1];
    const float* mmask    = (const float*)d_in[2];
    const float* Wp       = (const float*)d_in[3];
    const float* bp       = (const float*)d_in[4];
    const float* W1       = (const float*)d_in[5];
    const float* b1       = (const float*)d_in[6];
    const float* W2       = (const float*)d_in[7];
    const float* b2       = (const float*)d_in[8];
    float* out = (float*)d_out;

    static int attr_done = 0;
    if (!attr_done) {
        cudaFuncSetAttribute(ode_kernel,
                             cudaFuncAttributeMaxDynamicSharedMemorySize,
                             SMEM_BYTES);
        attr_done = 1;
    }

    build_band_kernel<<<NB, 384>>>(spk, mmask);
    proj_kernel<<<GRID, NT>>>(features, Wp, bp);
    ode_kernel<<<GRID, NT, SMEM_BYTES>>>(W1, b1, W2, b2, out);
}